// round 1
// baseline (speedup 1.0000x reference)
#include <cuda_runtime.h>
#include <cuda_bf16.h>
#include <math.h>

// ---------------------------------------------------------------------------
// Problem constants
// ---------------------------------------------------------------------------
#define BATCH    2
#define SEQ      2048
#define DMODEL   2048
#define DKV      512
#define DQ       1536
#define NHEADS   16
#define HDIM     128
#define ROWS     (BATCH*SEQ)            // 4096
#define QKDIM    256                    // concat(head, rope(head))
#define SCALE    0.0625f                // 1/sqrt(256)

#define OUT_SZ   (BATCH*SEQ*DMODEL)     // 8388608
#define CKV_SZ   (BATCH*SEQ*DKV)        // 2097152

// ---------------------------------------------------------------------------
// Scratch (no cudaMalloc allowed -> __device__ globals)
// ---------------------------------------------------------------------------
__device__ float g_cQ [ROWS*DQ];                 // 4096x1536
__device__ float g_kC [ROWS*DMODEL];             // 4096x2048
__device__ float g_vC [ROWS*DMODEL];             // 4096x2048
__device__ float g_qC [ROWS*DMODEL];             // 4096x2048
__device__ float g_q  [BATCH*NHEADS*SEQ*QKDIM];  // 16M
__device__ float g_k  [BATCH*NHEADS*SEQ*QKDIM];  // 16M
__device__ float g_ctx[ROWS*DMODEL];             // 4096x2048

// ---------------------------------------------------------------------------
// SGEMM: C[M,N] = A[M,K] @ B[K,N] + bias[N]   (all row-major, fp32)
// 128x128 block, BK=8, 256 threads, 8x8 per thread
// ---------------------------------------------------------------------------
__global__ __launch_bounds__(256) void sgemm_bias(
    int M, int N, int K,
    const float* __restrict__ A, const float* __restrict__ B,
    const float* __restrict__ bias, float* __restrict__ C)
{
    __shared__ float As[8][132];   // transposed, padded
    __shared__ float Bs[8][128];

    const int tid = threadIdx.x;
    const int bx = blockIdx.x, by = blockIdx.y;
    const int tx = tid & 15;       // 0..15  (N dir)
    const int ty = tid >> 4;       // 0..15  (M dir)

    const float* Ab = A + (size_t)by * 128 * K;
    const float* Bb = B + bx * 128;

    float acc[8][8];
#pragma unroll
    for (int i = 0; i < 8; i++)
#pragma unroll
        for (int j = 0; j < 8; j++) acc[i][j] = 0.f;

    const int arow = tid >> 1;           // 0..127
    const int acol = (tid & 1) * 4;      // 0 or 4
    const int brow = tid >> 5;           // 0..7
    const int bcol = (tid & 31) * 4;     // 0..124

    for (int k0 = 0; k0 < K; k0 += 8) {
        float4 av = *(const float4*)(Ab + (size_t)arow * K + k0 + acol);
        As[acol + 0][arow] = av.x;
        As[acol + 1][arow] = av.y;
        As[acol + 2][arow] = av.z;
        As[acol + 3][arow] = av.w;
        float4 bv = *(const float4*)(Bb + (size_t)(k0 + brow) * N + bcol);
        *(float4*)(&Bs[brow][bcol]) = bv;
        __syncthreads();

#pragma unroll
        for (int kk = 0; kk < 8; kk++) {
            float a[8], b[8];
            *(float4*)(a)     = *(const float4*)(&As[kk][ty * 8]);
            *(float4*)(a + 4) = *(const float4*)(&As[kk][ty * 8 + 4]);
            *(float4*)(b)     = *(const float4*)(&Bs[kk][tx * 8]);
            *(float4*)(b + 4) = *(const float4*)(&Bs[kk][tx * 8 + 4]);
#pragma unroll
            for (int i = 0; i < 8; i++)
#pragma unroll
                for (int j = 0; j < 8; j++)
                    acc[i][j] += a[i] * b[j];
        }
        __syncthreads();
    }

    const int cbase = bx * 128 + tx * 8;
    float bb[8];
#pragma unroll
    for (int j = 0; j < 8; j++) bb[j] = bias[cbase + j];
#pragma unroll
    for (int i = 0; i < 8; i++) {
        int r = by * 128 + ty * 8 + i;
        float4 o0, o1;
        o0.x = acc[i][0] + bb[0]; o0.y = acc[i][1] + bb[1];
        o0.z = acc[i][2] + bb[2]; o0.w = acc[i][3] + bb[3];
        o1.x = acc[i][4] + bb[4]; o1.y = acc[i][5] + bb[5];
        o1.z = acc[i][6] + bb[6]; o1.w = acc[i][7] + bb[7];
        *(float4*)(&C[(size_t)r * N + cbase])     = o0;
        *(float4*)(&C[(size_t)r * N + cbase + 4]) = o1;
    }
}

// ---------------------------------------------------------------------------
// Pack q: [B,S,H*128] -> [B,H,S,256] with rope in upper half; fold in SCALE
// one thread per rope pair: gid = b*(H*S*64) + h*(S*64) + s*64 + i
// ---------------------------------------------------------------------------
__global__ __launch_bounds__(256) void pack_q_kernel(
    const float* __restrict__ qC, float* __restrict__ q)
{
    int gid = blockIdx.x * blockDim.x + threadIdx.x;
    int i = gid & 63;
    int s = (gid >> 6) & (SEQ - 1);
    int h = (gid >> 17) & (NHEADS - 1);
    int b = gid >> 21;

    const float* src = qC + ((size_t)(b * SEQ + s)) * DMODEL + h * HDIM;
    float x1 = src[2 * i], x2 = src[2 * i + 1];

    float inv = powf(10000.0f, -(float)(2 * i) / 128.0f);
    float ang = (float)s * inv;
    float sn, cs; sincosf(ang, &sn, &cs);

    float* dst = q + (((size_t)(b * NHEADS + h)) * SEQ + s) * QKDIM;
    dst[2 * i]       = x1 * SCALE;
    dst[2 * i + 1]   = x2 * SCALE;
    dst[128 + 2 * i] = (x1 * cs - x2 * sn) * SCALE;
    dst[129 + 2 * i] = (x1 * sn + x2 * cs) * SCALE;
}

// ---------------------------------------------------------------------------
// Pack k: raw half from kC, rope half from kr_cache. No scale.
// ---------------------------------------------------------------------------
__global__ __launch_bounds__(256) void pack_k_kernel(
    const float* __restrict__ kC, const float* __restrict__ kr,
    float* __restrict__ k)
{
    int gid = blockIdx.x * blockDim.x + threadIdx.x;
    int i = gid & 63;
    int s = (gid >> 6) & (SEQ - 1);
    int h = (gid >> 17) & (NHEADS - 1);
    int b = gid >> 21;

    size_t soff = ((size_t)(b * SEQ + s)) * DMODEL + h * HDIM;
    const float* raw = kC + soff;
    const float* rot = kr + soff;
    float x1 = rot[2 * i], x2 = rot[2 * i + 1];

    float inv = powf(10000.0f, -(float)(2 * i) / 128.0f);
    float ang = (float)s * inv;
    float sn, cs; sincosf(ang, &sn, &cs);

    float* dst = k + (((size_t)(b * NHEADS + h)) * SEQ + s) * QKDIM;
    dst[2 * i]       = raw[2 * i];
    dst[2 * i + 1]   = raw[2 * i + 1];
    dst[128 + 2 * i] = x1 * cs - x2 * sn;
    dst[129 + 2 * i] = x1 * sn + x2 * cs;
}

// ---------------------------------------------------------------------------
// Flash attention (fp32, causal). BM=BN=64, 256 threads.
// Each thread: 2 q-rows (rp=tid/8), 8 score cols / 16 v cols (cg=tid%8).
// q already scaled. v read directly from vC [B,S,2048].
// ctx written to [B,S,H*128] layout for the output GEMM.
// ---------------------------------------------------------------------------
#define QS_LD 260
#define VS_LD 132
#define PS_LD 68
#define FL_SMEM ((64*QS_LD + 64*QS_LD + 64*VS_LD + 64*PS_LD) * 4)

__global__ __launch_bounds__(256) void flash_kernel(
    const float* __restrict__ q,    // [B,H,S,256] scaled
    const float* __restrict__ kk,   // [B,H,S,256]
    const float* __restrict__ vC,   // [B,S,2048]
    float* __restrict__ ctx)        // [B,S,2048]
{
    extern __shared__ float sm[];
    float* qs = sm;                   // 64 x 260
    float* ks = qs + 64 * QS_LD;      // 64 x 260
    float* vs = ks + 64 * QS_LD;      // 64 x 132
    float* ps = vs + 64 * VS_LD;      // 64 x 68

    const int tid = threadIdx.x;
    const int qt  = blockIdx.x;       // q tile 0..31
    const int bh  = blockIdx.y;       // 0..31
    const int b = bh >> 4, h = bh & 15;

    // load q tile (64 rows x 256)
    const float* qbase = q + ((size_t)bh * SEQ + qt * 64) * QKDIM;
    for (int i = tid; i < 64 * 64; i += 256) {
        int r = i >> 6, c4 = i & 63;
        *(float4*)(&qs[r * QS_LD + c4 * 4]) =
            *(const float4*)(qbase + (size_t)r * QKDIM + c4 * 4);
    }

    const int rp = tid >> 3;          // 0..31
    const int cg = tid & 7;           // 0..7
    const int r0 = rp * 2, r1 = r0 + 1;
    const int qg0 = qt * 64 + r0, qg1 = qg0 + 1;

    float m0 = -1e30f, m1 = -1e30f, l0 = 0.f, l1 = 0.f;
    float acc0[16], acc1[16];
#pragma unroll
    for (int i = 0; i < 16; i++) { acc0[i] = 0.f; acc1[i] = 0.f; }

    __syncthreads();

    for (int kt = 0; kt <= qt; kt++) {
        // load k tile and v tile
        const float* kbase = kk + ((size_t)bh * SEQ + kt * 64) * QKDIM;
        for (int i = tid; i < 64 * 64; i += 256) {
            int r = i >> 6, c4 = i & 63;
            *(float4*)(&ks[r * QS_LD + c4 * 4]) =
                *(const float4*)(kbase + (size_t)r * QKDIM + c4 * 4);
        }
        const float* vbase = vC + ((size_t)b * SEQ + kt * 64) * DMODEL + h * HDIM;
        for (int i = tid; i < 64 * 32; i += 256) {
            int r = i >> 5, d4 = i & 31;
            *(float4*)(&vs[r * VS_LD + d4 * 4]) =
                *(const float4*)(vbase + (size_t)r * DMODEL + d4 * 4);
        }
        __syncthreads();

        // ---- scores: s[r][c] = q_r . k_c ----
        float s0[8], s1[8];
#pragma unroll
        for (int j = 0; j < 8; j++) { s0[j] = 0.f; s1[j] = 0.f; }
        const float* qr0 = &qs[r0 * QS_LD];
        const float* qr1 = &qs[r1 * QS_LD];
#pragma unroll 4
        for (int d = 0; d < QKDIM; d++) {
            float a0 = qr0[d], a1 = qr1[d];
#pragma unroll
            for (int j = 0; j < 8; j++) {
                float kv = ks[(cg + 8 * j) * QS_LD + d];
                s0[j] += a0 * kv;
                s1[j] += a1 * kv;
            }
        }
        // causal mask (only diagonal tile can be partial)
        if (kt == qt) {
            int cbase = kt * 64 + cg;
#pragma unroll
            for (int j = 0; j < 8; j++) {
                int c = cbase + 8 * j;
                if (c > qg0) s0[j] = -1e30f;
                if (c > qg1) s1[j] = -1e30f;
            }
        }
        // row max (8 lanes per row-group)
        float t0 = s0[0], t1 = s1[0];
#pragma unroll
        for (int j = 1; j < 8; j++) { t0 = fmaxf(t0, s0[j]); t1 = fmaxf(t1, s1[j]); }
        for (int o = 1; o < 8; o <<= 1) {
            t0 = fmaxf(t0, __shfl_xor_sync(0xffffffffu, t0, o));
            t1 = fmaxf(t1, __shfl_xor_sync(0xffffffffu, t1, o));
        }
        float mn0 = fmaxf(m0, t0), mn1 = fmaxf(m1, t1);
        float f0 = __expf(m0 - mn0), f1 = __expf(m1 - mn1);
        m0 = mn0; m1 = mn1;

        float sum0 = 0.f, sum1 = 0.f;
#pragma unroll
        for (int j = 0; j < 8; j++) {
            float p0 = __expf(s0[j] - mn0);
            float p1 = __expf(s1[j] - mn1);
            ps[r0 * PS_LD + cg + 8 * j] = p0;
            ps[r1 * PS_LD + cg + 8 * j] = p1;
            sum0 += p0; sum1 += p1;
        }
        for (int o = 1; o < 8; o <<= 1) {
            sum0 += __shfl_xor_sync(0xffffffffu, sum0, o);
            sum1 += __shfl_xor_sync(0xffffffffu, sum1, o);
        }
        l0 = l0 * f0 + sum0;
        l1 = l1 * f1 + sum1;
#pragma unroll
        for (int i = 0; i < 16; i++) { acc0[i] *= f0; acc1[i] *= f1; }
        __syncthreads();   // ps visible to all

        // ---- ctx += P @ V ----   thread owns d = cg + 8*i
#pragma unroll 2
        for (int c = 0; c < 64; c++) {
            float p0 = ps[r0 * PS_LD + c];
            float p1 = ps[r1 * PS_LD + c];
            const float* vr = &vs[c * VS_LD + cg];
#pragma unroll
            for (int i = 0; i < 16; i++) {
                float vv = vr[8 * i];
                acc0[i] += p0 * vv;
                acc1[i] += p1 * vv;
            }
        }
        __syncthreads();   // ks/vs/ps reusable
    }

    float inv0 = 1.f / l0, inv1 = 1.f / l1;
    float* o0 = ctx + ((size_t)b * SEQ + qg0) * DMODEL + h * HDIM + cg;
    float* o1 = ctx + ((size_t)b * SEQ + qg1) * DMODEL + h * HDIM + cg;
#pragma unroll
    for (int i = 0; i < 16; i++) {
        o0[8 * i] = acc0[i] * inv0;
        o1[8 * i] = acc1[i] * inv1;
    }
}

// ---------------------------------------------------------------------------
// Launch
// ---------------------------------------------------------------------------
extern "C" void kernel_launch(void* const* d_in, const int* in_sizes, int n_in,
                              void* d_out, int out_size)
{
    const float* h     = (const float*)d_in[0];
    const float* W_DKV = (const float*)d_in[1];
    const float* b_DKV = (const float*)d_in[2];
    const float* W_UK  = (const float*)d_in[3];
    const float* b_UK  = (const float*)d_in[4];
    const float* W_UV  = (const float*)d_in[5];
    const float* b_UV  = (const float*)d_in[6];
    const float* W_DQ  = (const float*)d_in[7];
    const float* b_DQ  = (const float*)d_in[8];
    const float* W_UQ  = (const float*)d_in[9];
    const float* b_UQ  = (const float*)d_in[10];
    const float* W_KR  = (const float*)d_in[11];
    const float* b_KR  = (const float*)d_in[12];
    const float* W_O   = (const float*)d_in[13];
    const float* b_O   = (const float*)d_in[14];

    float* out = (float*)d_out;            // [0, OUT_SZ)
    float* cKV = out + OUT_SZ;             // [OUT_SZ, OUT_SZ+CKV_SZ)
    float* kr  = cKV + CKV_SZ;             // kr_cache

    float *p_cQ, *p_kC, *p_vC, *p_qC, *p_q, *p_k, *p_ctx;
    cudaGetSymbolAddress((void**)&p_cQ,  g_cQ);
    cudaGetSymbolAddress((void**)&p_kC,  g_kC);
    cudaGetSymbolAddress((void**)&p_vC,  g_vC);
    cudaGetSymbolAddress((void**)&p_qC,  g_qC);
    cudaGetSymbolAddress((void**)&p_q,   g_q);
    cudaGetSymbolAddress((void**)&p_k,   g_k);
    cudaGetSymbolAddress((void**)&p_ctx, g_ctx);

    cudaFuncSetAttribute(flash_kernel,
                         cudaFuncAttributeMaxDynamicSharedMemorySize, FL_SMEM);

    // projections
    sgemm_bias<<<dim3(DKV/128,    ROWS/128), 256>>>(ROWS, DKV,    DMODEL, h,    W_DKV, b_DKV, cKV);
    sgemm_bias<<<dim3(DMODEL/128, ROWS/128), 256>>>(ROWS, DMODEL, DMODEL, h,    W_KR,  b_KR,  kr);
    sgemm_bias<<<dim3(DQ/128,     ROWS/128), 256>>>(ROWS, DQ,     DMODEL, h,    W_DQ,  b_DQ,  p_cQ);
    sgemm_bias<<<dim3(DMODEL/128, ROWS/128), 256>>>(ROWS, DMODEL, DKV,    cKV,  W_UK,  b_UK,  p_kC);
    sgemm_bias<<<dim3(DMODEL/128, ROWS/128), 256>>>(ROWS, DMODEL, DKV,    cKV,  W_UV,  b_UV,  p_vC);
    sgemm_bias<<<dim3(DMODEL/128, ROWS/128), 256>>>(ROWS, DMODEL, DQ,     p_cQ, W_UQ,  b_UQ,  p_qC);

    // rope + repack
    int pack_threads = BATCH * NHEADS * SEQ * 64;   // 4194304
    pack_q_kernel<<<pack_threads / 256, 256>>>(p_qC, p_q);
    pack_k_kernel<<<pack_threads / 256, 256>>>(p_kC, kr, p_k);

    // attention
    flash_kernel<<<dim3(SEQ/64, BATCH*NHEADS), 256, FL_SMEM>>>(p_q, p_k, p_vC, p_ctx);

    // output projection
    sgemm_bias<<<dim3(DMODEL/128, ROWS/128), 256>>>(ROWS, DMODEL, DMODEL, p_ctx, W_O, b_O, out);
}